// round 12
// baseline (speedup 1.0000x reference)
#include <cuda_runtime.h>
#include <cstdint>

#define NN 50000
#define EE 800000
#define ETOT (EE + NN)
#define DD 128
#define NROWS_PAD 50048
#define NBSCAN ((NN + 1023) / 1024)

// ---------------- static device scratch ----------------
__device__ uint32_t g_htf[NROWS_PAD * DD];   // tf32(relu(h)) — produced by attn, consumed by gemm A
__device__ float g_xl[NN * DD];
__device__ float g_xr[NN * DD];
__device__ int   g_deg[NN];
__device__ int   g_offs[NN + 1];
__device__ int   g_srcs[ETOT];
__device__ int   g_bsums[NBSCAN];
// pre-converted tf32 weights: [layer][k][col 0..255 = Wl|Wr]
__device__ uint32_t g_WH[4 * 128 * 256];

__device__ __forceinline__ uint32_t f2tf32(float x) {
    uint32_t r;
    asm volatile("cvt.rna.tf32.f32 %0, %1;" : "=r"(r) : "f"(x));
    return r;
}

// ---------------- CSR build ----------------
__global__ void zero_counts() {
    int i = blockIdx.x * blockDim.x + threadIdx.x;
    if (i < NN) g_deg[i] = 0;
}

__global__ void count_edges(const int* __restrict__ ei) {
    int t = blockIdx.x * blockDim.x + threadIdx.x;
    if (t < ETOT) {
        int dst = (t < EE) ? ei[EE + t] : (t - EE);
        atomicAdd(&g_deg[dst], 1);
    }
}

__global__ void scan_block() {
    __shared__ int sm[256];
    int t = threadIdx.x;
    int base = blockIdx.x * 1024 + t * 4;
    int v0 = (base + 0 < NN) ? g_deg[base + 0] : 0;
    int v1 = (base + 1 < NN) ? g_deg[base + 1] : 0;
    int v2 = (base + 2 < NN) ? g_deg[base + 2] : 0;
    int v3 = (base + 3 < NN) ? g_deg[base + 3] : 0;
    v1 += v0; v2 += v1; v3 += v2;
    sm[t] = v3;
    __syncthreads();
    #pragma unroll
    for (int off = 1; off < 256; off <<= 1) {
        int add = (t >= off) ? sm[t - off] : 0;
        __syncthreads();
        sm[t] += add;
        __syncthreads();
    }
    int prev = (t > 0) ? sm[t - 1] : 0;
    if (base + 0 < NN) g_offs[base + 0] = prev + v0;
    if (base + 1 < NN) g_offs[base + 1] = prev + v1;
    if (base + 2 < NN) g_offs[base + 2] = prev + v2;
    if (base + 3 < NN) g_offs[base + 3] = prev + v3;
    if (t == 255) g_bsums[blockIdx.x] = sm[255];
}

__global__ void scan_spine() {
    __shared__ int sm[64];
    int t = threadIdx.x;
    sm[t] = (t < NBSCAN) ? g_bsums[t] : 0;
    __syncthreads();
    #pragma unroll
    for (int off = 1; off < 64; off <<= 1) {
        int add = (t >= off) ? sm[t - off] : 0;
        __syncthreads();
        sm[t] += add;
        __syncthreads();
    }
    if (t < NBSCAN) g_bsums[t] = (t > 0) ? sm[t - 1] : 0;
}

__global__ void scan_fix() {
    int i = blockIdx.x * blockDim.x + threadIdx.x;
    if (i < NN) g_offs[i] = g_offs[i] - g_deg[i] + g_bsums[i >> 10];   // exclusive start
}

// fill bumps g_offs[dst]; afterwards g_offs[d] = end of segment d
__global__ void fill_edges(const int* __restrict__ ei) {
    int t = blockIdx.x * blockDim.x + threadIdx.x;
    if (t < ETOT) {
        int src, dst;
        if (t < EE) { src = ei[t]; dst = ei[EE + t]; }
        else        { src = t - EE; dst = src; }
        int pos = atomicAdd(&g_offs[dst], 1);
        g_srcs[pos] = src;
    }
}

// ---------------- weight pre-convert (tf32) ----------------
__global__ void split_w(const float* __restrict__ Wl, const float* __restrict__ Wr) {
    int i = blockIdx.x * blockDim.x + threadIdx.x;
    if (i >= 4 * 128 * 256) return;
    int layer = i >> 15;
    int rem = i & 32767;
    int k = rem >> 8;
    int c = rem & 255;
    float v = (c < 128) ? Wl[layer * 16384 + k * 128 + c]
                        : Wr[layer * 16384 + k * 128 + (c - 128)];
    g_WH[i] = f2tf32(v);
}

// ---------------- layer 0 GEMM (K=7) ----------------
__global__ void gemm0(const float* __restrict__ x,
                      const float* __restrict__ Wl0, const float* __restrict__ Wr0,
                      const float* __restrict__ bl0, const float* __restrict__ br0) {
    int node = blockIdx.x;
    int j = threadIdx.x;
    __shared__ float xs[7];
    if (j < 7) xs[j] = x[node * 7 + j];
    __syncthreads();
    const float* W = (j < 128) ? Wl0 : Wr0;
    int c = j & 127;
    float acc = (j < 128) ? bl0[c] : br0[c];
    #pragma unroll
    for (int k = 0; k < 7; k++) acc += xs[k] * W[k * 128 + c];
    if (j < 128) g_xl[node * DD + c] = acc;
    else         g_xr[node * DD + c] = acc;
}

// ---------------- TC GEMM v7: 64x256 tile, occ 2, full cp.async, single-barrier DB ----------------
#define KC 16
// stage words: As [64][20] = 1280 | Bs [16][264] = 4224
#define STAGE_WORDS 5504
#define OFF_B 1280
#define GEMM_SMEM_BYTES (2 * STAGE_WORDS * 4)

__device__ __forceinline__ void mma_tf32(float c[4], const uint32_t a[4], uint32_t b0, uint32_t b1) {
    asm volatile(
        "mma.sync.aligned.m16n8k8.row.col.f32.tf32.tf32.f32 "
        "{%0,%1,%2,%3}, {%4,%5,%6,%7}, {%8,%9}, {%0,%1,%2,%3};"
        : "+f"(c[0]), "+f"(c[1]), "+f"(c[2]), "+f"(c[3])
        : "r"(a[0]), "r"(a[1]), "r"(a[2]), "r"(a[3]), "r"(b0), "r"(b1));
}

__device__ __forceinline__ void cp16(uint32_t* dst_smem, const uint32_t* src_gmem) {
    uint32_t saddr = (uint32_t)__cvta_generic_to_shared(dst_smem);
    asm volatile("cp.async.cg.shared.global [%0], [%1], 16;" :: "r"(saddr), "l"(src_gmem));
}

__global__ __launch_bounds__(256, 2) void gemm_tc(int layer,
                                                  const float* __restrict__ bl_,
                                                  const float* __restrict__ br_) {
    extern __shared__ uint32_t smem[];

    int tid  = threadIdx.x;
    int lane = tid & 31;
    int wid  = tid >> 5;
    int g    = lane >> 2;
    int tig  = lane & 3;
    int wm   = wid >> 2;                // 0..1  (rows 32 each)
    int wn   = wid & 3;                 // 0..3  (cols 64 each)
    int m_base = wm * 32;
    int n_base = wn * 64;
    int row0 = blockIdx.x * 64;

    const uint32_t* Wbase = g_WH + layer * 32768;

    float c[2][8][4];
    #pragma unroll
    for (int mi = 0; mi < 2; mi++)
        #pragma unroll
        for (int ni = 0; ni < 8; ni++)
            #pragma unroll
            for (int q = 0; q < 4; q++) c[mi][ni][q] = 0.f;

    int ar  = tid >> 2;                 // A: row 0..63
    int akq = (tid & 3) * 4;            // A: k offset (4 words)
    int bk  = tid >> 4;                 // B: k 0..15
    int bc  = (tid & 15) * 16;          // B: col offset (16 words)
    const uint32_t* a_gp = &g_htf[(size_t)(row0 + ar) * DD + akq];

    // prologue: stage 0
    {
        uint32_t* As = smem;
        uint32_t* Bs = smem + OFF_B;
        cp16(&As[ar * 20 + akq], &a_gp[0]);
        const uint32_t* sB = Wbase + bk * 256 + bc;
        cp16(&Bs[bk * 264 + bc],      &sB[0]);
        cp16(&Bs[bk * 264 + bc + 4],  &sB[4]);
        cp16(&Bs[bk * 264 + bc + 8],  &sB[8]);
        cp16(&Bs[bk * 264 + bc + 12], &sB[12]);
        asm volatile("cp.async.commit_group;");
    }

    for (int it = 0; it < 8; it++) {
        uint32_t* As = smem + (it & 1) * STAGE_WORDS;
        uint32_t* Bs = As + OFF_B;

        asm volatile("cp.async.wait_group 0;");
        __syncthreads();

        if (it < 7) {
            int k0n = (it + 1) * KC;
            uint32_t* An = smem + ((it + 1) & 1) * STAGE_WORDS;
            uint32_t* Bn = An + OFF_B;
            cp16(&An[ar * 20 + akq], &a_gp[k0n]);
            const uint32_t* sB = Wbase + (k0n + bk) * 256 + bc;
            cp16(&Bn[bk * 264 + bc],      &sB[0]);
            cp16(&Bn[bk * 264 + bc + 4],  &sB[4]);
            cp16(&Bn[bk * 264 + bc + 8],  &sB[8]);
            cp16(&Bn[bk * 264 + bc + 12], &sB[12]);
            asm volatile("cp.async.commit_group;");
        }

        #pragma unroll
        for (int ks = 0; ks < KC; ks += 8) {
            uint32_t a[2][4];
            #pragma unroll
            for (int mi = 0; mi < 2; mi++) {
                int r = m_base + mi * 16 + g;
                a[mi][0] = As[r * 20 + ks + tig];
                a[mi][1] = As[(r + 8) * 20 + ks + tig];
                a[mi][2] = As[r * 20 + ks + tig + 4];
                a[mi][3] = As[(r + 8) * 20 + ks + tig + 4];
            }
            #pragma unroll
            for (int ni = 0; ni < 8; ni++) {
                int cc = n_base + ni * 8 + g;
                uint32_t b0 = Bs[(ks + tig) * 264 + cc];
                uint32_t b1 = Bs[(ks + tig + 4) * 264 + cc];
                #pragma unroll
                for (int mi = 0; mi < 2; mi++)
                    mma_tf32(c[mi][ni], a[mi], b0, b1);
            }
        }
    }

    // --- epilogue: cols <128 -> g_xl (+bl), cols >=128 -> g_xr (+br) ---
    #pragma unroll
    for (int ni = 0; ni < 8; ni++) {
        int cn = n_base + ni * 8 + tig * 2;
        int cl = (cn < 128) ? cn : (cn - 128);
        const float* bias = (cn < 128) ? bl_ : br_;
        float* dst = (cn < 128) ? g_xl : g_xr;
        float b0 = bias[cl], b1 = bias[cl + 1];
        #pragma unroll
        for (int mi = 0; mi < 2; mi++) {
            int ra = row0 + m_base + mi * 16 + g;
            int rb = ra + 8;
            if (ra < NN)
                *(float2*)&dst[(size_t)ra * DD + cl] = make_float2(c[mi][ni][0] + b0, c[mi][ni][1] + b1);
            if (rb < NN)
                *(float2*)&dst[(size_t)rb * DD + cl] = make_float2(c[mi][ni][2] + b0, c[mi][ni][3] + b1);
        }
    }
}

// ---------------- attention: warp per node, no-max softmax, ILP-4 + prefetch ----------------
__device__ __forceinline__ float dleaky(float4 c, float4 xr, float4 a, float d) {
    float v;
    v = c.x + xr.x; v = (v > 0.f) ? v : 0.2f * v; d = fmaf(v, a.x, d);
    v = c.y + xr.y; v = (v > 0.f) ? v : 0.2f * v; d = fmaf(v, a.y, d);
    v = c.z + xr.z; v = (v > 0.f) ? v : 0.2f * v; d = fmaf(v, a.z, d);
    v = c.w + xr.w; v = (v > 0.f) ? v : 0.2f * v; d = fmaf(v, a.w, d);
    return d;
}

__global__ void attn(const float* __restrict__ avec, const float* __restrict__ bvec,
                     float* __restrict__ outp) {
    const unsigned FULL = 0xffffffffu;
    int w = (blockIdx.x * blockDim.x + threadIdx.x) >> 5;
    if (w >= NN) return;
    int lane = threadIdx.x & 31;

    float4 xr4 = *(float4*)&g_xr[(size_t)w * DD + lane * 4];
    float4 a4  = *(const float4*)&avec[lane * 4];

    int p   = (w > 0) ? g_offs[w - 1] : 0;
    int end = g_offs[w];
    float s = 0.f;
    float ax = 0.f, ay = 0.f, az = 0.f, aw = 0.f;

    int p4end = p + ((end - p) & ~3);

    float4 c0, c1, c2, c3;
    if (p < p4end) {
        int s0 = g_srcs[p], s1 = g_srcs[p + 1], s2 = g_srcs[p + 2], s3 = g_srcs[p + 3];
        c0 = *(const float4*)&g_xl[(size_t)s0 * DD + lane * 4];
        c1 = *(const float4*)&g_xl[(size_t)s1 * DD + lane * 4];
        c2 = *(const float4*)&g_xl[(size_t)s2 * DD + lane * 4];
        c3 = *(const float4*)&g_xl[(size_t)s3 * DD + lane * 4];
    }

    while (p < p4end) {
        float4 u0 = c0, u1 = c1, u2 = c2, u3 = c3;
        int pn = p + 4;
        if (pn < p4end) {
            int s0 = g_srcs[pn], s1 = g_srcs[pn + 1], s2 = g_srcs[pn + 2], s3 = g_srcs[pn + 3];
            c0 = *(const float4*)&g_xl[(size_t)s0 * DD + lane * 4];
            c1 = *(const float4*)&g_xl[(size_t)s1 * DD + lane * 4];
            c2 = *(const float4*)&g_xl[(size_t)s2 * DD + lane * 4];
            c3 = *(const float4*)&g_xl[(size_t)s3 * DD + lane * 4];
        }

        float d0 = dleaky(u0, xr4, a4, 0.f);
        float d1 = dleaky(u1, xr4, a4, 0.f);
        float d2 = dleaky(u2, xr4, a4, 0.f);
        float d3 = dleaky(u3, xr4, a4, 0.f);

        #pragma unroll
        for (int off = 16; off >= 1; off >>= 1) {
            d0 += __shfl_xor_sync(FULL, d0, off);
            d1 += __shfl_xor_sync(FULL, d1, off);
            d2 += __shfl_xor_sync(FULL, d2, off);
            d3 += __shfl_xor_sync(FULL, d3, off);
        }

        float w0 = __expf(d0), w1 = __expf(d1), w2 = __expf(d2), w3 = __expf(d3);
        s += (w0 + w1) + (w2 + w3);
        ax += w0 * u0.x + w1 * u1.x + w2 * u2.x + w3 * u3.x;
        ay += w0 * u0.y + w1 * u1.y + w2 * u2.y + w3 * u3.y;
        az += w0 * u0.z + w1 * u1.z + w2 * u2.z + w3 * u3.z;
        aw += w0 * u0.w + w1 * u1.w + w2 * u2.w + w3 * u3.w;
        p = pn;
    }

    while (p < end) {
        int s0 = g_srcs[p];
        float4 u0 = *(const float4*)&g_xl[(size_t)s0 * DD + lane * 4];
        float d0 = dleaky(u0, xr4, a4, 0.f);
        #pragma unroll
        for (int off = 16; off >= 1; off >>= 1)
            d0 += __shfl_xor_sync(FULL, d0, off);
        float w0 = __expf(d0);
        s += w0;
        ax += w0 * u0.x;
        ay += w0 * u0.y;
        az += w0 * u0.z;
        aw += w0 * u0.w;
        p++;
    }

    float inv = 1.f / s;
    float4 b4 = *(const float4*)&bvec[lane * 4];
    float4 r = make_float4(ax * inv + b4.x, ay * inv + b4.y,
                           az * inv + b4.z, aw * inv + b4.w);
    if (outp) {
        *(float4*)&outp[(size_t)w * DD + lane * 4] = r;
    } else {
        uint4 t;
        t.x = f2tf32(fmaxf(r.x, 0.f));
        t.y = f2tf32(fmaxf(r.y, 0.f));
        t.z = f2tf32(fmaxf(r.z, 0.f));
        t.w = f2tf32(fmaxf(r.w, 0.f));
        *(uint4*)&g_htf[(size_t)w * DD + lane * 4] = t;
    }
}

// ---------------- launch ----------------
extern "C" void kernel_launch(void* const* d_in, const int* in_sizes, int n_in,
                              void* d_out, int out_size) {
    const float* x    = (const float*)d_in[0];
    const int*   ei   = (const int*)d_in[1];
    const float* Wl0  = (const float*)d_in[2];
    const float* Wr0  = (const float*)d_in[3];
    const float* bl0  = (const float*)d_in[4];
    const float* br0  = (const float*)d_in[5];
    const float* Wl   = (const float*)d_in[6];
    const float* Wr   = (const float*)d_in[7];
    const float* bl   = (const float*)d_in[8];
    const float* br   = (const float*)d_in[9];
    const float* att  = (const float*)d_in[10];
    const float* bias = (const float*)d_in[11];
    float* out = (float*)d_out;

    cudaFuncSetAttribute(gemm_tc, cudaFuncAttributeMaxDynamicSharedMemorySize, GEMM_SMEM_BYTES);

    zero_counts<<<(NN + 255) / 256, 256>>>();
    count_edges<<<(ETOT + 255) / 256, 256>>>(ei);
    scan_block<<<NBSCAN, 256>>>();
    scan_spine<<<1, 64>>>();
    scan_fix<<<(NN + 255) / 256, 256>>>();
    fill_edges<<<(ETOT + 255) / 256, 256>>>(ei);
    split_w<<<(4 * 128 * 256 + 255) / 256, 256>>>(Wl, Wr);

    const int attn_blocks = (NN * 32 + 255) / 256;
    const int tc_blocks = (NN + 63) / 64;

    gemm0<<<NN, 256>>>(x, Wl0, Wr0, bl0, br0);
    attn<<<attn_blocks, 256>>>(att, bias, nullptr);

    for (int t = 1; t < 5; t++) {
        gemm_tc<<<tc_blocks, 256, GEMM_SMEM_BYTES>>>(t - 1, bl + (size_t)(t - 1) * 128,
                                                     br + (size_t)(t - 1) * 128);
        attn<<<attn_blocks, 256>>>(att + (size_t)t * 128, bias + (size_t)t * 128,
                                   (t == 4) ? out : nullptr);
    }
}

// round 13
// speedup vs baseline: 1.0902x; 1.0902x over previous
#include <cuda_runtime.h>
#include <cstdint>

#define NN 50000
#define EE 800000
#define ETOT (EE + NN)
#define DD 128
#define NROWS_PAD 50048
#define NBSCAN ((NN + 1023) / 1024)

// ---------------- static device scratch ----------------
__device__ uint32_t g_htf[NROWS_PAD * DD];   // tf32(relu(h)) — produced by attn, consumed by gemm A
__device__ float g_xl[NN * DD];
__device__ float g_xr[NN * DD];
__device__ int   g_deg[NN];
__device__ int   g_offs[NN + 1];
__device__ int   g_srcs[ETOT];
__device__ int   g_bsums[NBSCAN];
// pre-converted tf32 weights: [layer][k][col 0..255 = Wl|Wr]
__device__ uint32_t g_WH[4 * 128 * 256];

__device__ __forceinline__ uint32_t f2tf32(float x) {
    uint32_t r;
    asm volatile("cvt.rna.tf32.f32 %0, %1;" : "=r"(r) : "f"(x));
    return r;
}

// ---------------- CSR build ----------------
__global__ void zero_counts() {
    int i = blockIdx.x * blockDim.x + threadIdx.x;
    if (i < NN) g_deg[i] = 0;
}

__global__ void count_edges(const int* __restrict__ ei) {
    int t = blockIdx.x * blockDim.x + threadIdx.x;
    if (t < ETOT) {
        int dst = (t < EE) ? ei[EE + t] : (t - EE);
        atomicAdd(&g_deg[dst], 1);
    }
}

__global__ void scan_block() {
    __shared__ int sm[256];
    int t = threadIdx.x;
    int base = blockIdx.x * 1024 + t * 4;
    int v0 = (base + 0 < NN) ? g_deg[base + 0] : 0;
    int v1 = (base + 1 < NN) ? g_deg[base + 1] : 0;
    int v2 = (base + 2 < NN) ? g_deg[base + 2] : 0;
    int v3 = (base + 3 < NN) ? g_deg[base + 3] : 0;
    v1 += v0; v2 += v1; v3 += v2;
    sm[t] = v3;
    __syncthreads();
    #pragma unroll
    for (int off = 1; off < 256; off <<= 1) {
        int add = (t >= off) ? sm[t - off] : 0;
        __syncthreads();
        sm[t] += add;
        __syncthreads();
    }
    int prev = (t > 0) ? sm[t - 1] : 0;
    if (base + 0 < NN) g_offs[base + 0] = prev + v0;
    if (base + 1 < NN) g_offs[base + 1] = prev + v1;
    if (base + 2 < NN) g_offs[base + 2] = prev + v2;
    if (base + 3 < NN) g_offs[base + 3] = prev + v3;
    if (t == 255) g_bsums[blockIdx.x] = sm[255];
}

__global__ void scan_spine() {
    __shared__ int sm[64];
    int t = threadIdx.x;
    sm[t] = (t < NBSCAN) ? g_bsums[t] : 0;
    __syncthreads();
    #pragma unroll
    for (int off = 1; off < 64; off <<= 1) {
        int add = (t >= off) ? sm[t - off] : 0;
        __syncthreads();
        sm[t] += add;
        __syncthreads();
    }
    if (t < NBSCAN) g_bsums[t] = (t > 0) ? sm[t - 1] : 0;
}

__global__ void scan_fix() {
    int i = blockIdx.x * blockDim.x + threadIdx.x;
    if (i < NN) g_offs[i] = g_offs[i] - g_deg[i] + g_bsums[i >> 10];   // exclusive start
}

// fill bumps g_offs[dst]; afterwards g_offs[d] = end of segment d
__global__ void fill_edges(const int* __restrict__ ei) {
    int t = blockIdx.x * blockDim.x + threadIdx.x;
    if (t < ETOT) {
        int src, dst;
        if (t < EE) { src = ei[t]; dst = ei[EE + t]; }
        else        { src = t - EE; dst = src; }
        int pos = atomicAdd(&g_offs[dst], 1);
        g_srcs[pos] = src;
    }
}

// ---------------- weight pre-convert (tf32) ----------------
__global__ void split_w(const float* __restrict__ Wl, const float* __restrict__ Wr) {
    int i = blockIdx.x * blockDim.x + threadIdx.x;
    if (i >= 4 * 128 * 256) return;
    int layer = i >> 15;
    int rem = i & 32767;
    int k = rem >> 8;
    int c = rem & 255;
    float v = (c < 128) ? Wl[layer * 16384 + k * 128 + c]
                        : Wr[layer * 16384 + k * 128 + (c - 128)];
    g_WH[i] = f2tf32(v);
}

// ---------------- layer 0 GEMM (K=7) ----------------
__global__ void gemm0(const float* __restrict__ x,
                      const float* __restrict__ Wl0, const float* __restrict__ Wr0,
                      const float* __restrict__ bl0, const float* __restrict__ br0) {
    int node = blockIdx.x;
    int j = threadIdx.x;
    __shared__ float xs[7];
    if (j < 7) xs[j] = x[node * 7 + j];
    __syncthreads();
    const float* W = (j < 128) ? Wl0 : Wr0;
    int c = j & 127;
    float acc = (j < 128) ? bl0[c] : br0[c];
    #pragma unroll
    for (int k = 0; k < 7; k++) acc += xs[k] * W[k * 128 + c];
    if (j < 128) g_xl[node * DD + c] = acc;
    else         g_xr[node * DD + c] = acc;
}

// ---------------- TC GEMM (r10 config + 3-stage pipeline) ----------------
// Grid (391, 2): y=0 -> Wl -> g_xl, y=1 -> Wr -> g_xr. Tile 128x128, 8 warps (4x2).
#define KC 16
// stage words: As [128][20] = 2560 | BsH [16][136] = 2176
#define STAGE_WORDS 4736
#define OFF_BH 2560
#define NSTAGE 3
#define GEMM_SMEM_BYTES (NSTAGE * STAGE_WORDS * 4)

__device__ __forceinline__ void mma_tf32(float c[4], const uint32_t a[4], uint32_t b0, uint32_t b1) {
    asm volatile(
        "mma.sync.aligned.m16n8k8.row.col.f32.tf32.tf32.f32 "
        "{%0,%1,%2,%3}, {%4,%5,%6,%7}, {%8,%9}, {%0,%1,%2,%3};"
        : "+f"(c[0]), "+f"(c[1]), "+f"(c[2]), "+f"(c[3])
        : "r"(a[0]), "r"(a[1]), "r"(a[2]), "r"(a[3]), "r"(b0), "r"(b1));
}

__device__ __forceinline__ void cp16(uint32_t* dst_smem, const uint32_t* src_gmem) {
    uint32_t saddr = (uint32_t)__cvta_generic_to_shared(dst_smem);
    asm volatile("cp.async.cg.shared.global [%0], [%1], 16;" :: "r"(saddr), "l"(src_gmem));
}

__global__ __launch_bounds__(256, 2) void gemm_tc(int layer,
                                                  const float* __restrict__ bl_,
                                                  const float* __restrict__ br_) {
    extern __shared__ uint32_t smem[];

    int tid  = threadIdx.x;
    int lane = tid & 31;
    int wid  = tid >> 5;
    int g    = lane >> 2;
    int tig  = lane & 3;
    int wm   = wid >> 1;                // 0..3
    int wn   = wid & 1;                 // 0..1
    int m_base = wm * 32;
    int n_base = wn * 64;
    int row0 = blockIdx.x * 128;
    int yhalf = blockIdx.y;

    const uint32_t* WHbase = g_WH + layer * 32768 + yhalf * 128;

    float c[2][8][4];
    #pragma unroll
    for (int mi = 0; mi < 2; mi++)
        #pragma unroll
        for (int ni = 0; ni < 8; ni++)
            #pragma unroll
            for (int q = 0; q < 4; q++) c[mi][ni][q] = 0.f;

    int ar  = tid >> 1;                     // A: row 0..127
    int akq = (tid & 1) * 8;                // A: k offset (8 words)
    int bk  = tid >> 4;                     // B: k 0..15
    int bc  = (tid & 15) * 8;               // B: col offset (8 words)
    const uint32_t* a_gp = &g_htf[(size_t)(row0 + ar) * DD + akq];

    // prologue: stages 0 and 1
    #pragma unroll
    for (int st = 0; st < 2; st++) {
        uint32_t* As = smem + st * STAGE_WORDS;
        uint32_t* BH = As + OFF_BH;
        int k0 = st * KC;
        cp16(&As[ar * 20 + akq],     &a_gp[k0]);
        cp16(&As[ar * 20 + akq + 4], &a_gp[k0 + 4]);
        const uint32_t* sH = WHbase + (k0 + bk) * 256 + bc;
        cp16(&BH[bk * 136 + bc],     &sH[0]);
        cp16(&BH[bk * 136 + bc + 4], &sH[4]);
        asm volatile("cp.async.commit_group;");
    }

    int buf = 0;
    for (int it = 0; it < 8; it++) {
        uint32_t* As  = smem + buf * STAGE_WORDS;
        uint32_t* BsH = As + OFF_BH;

        asm volatile("cp.async.wait_group 1;");   // stage(it) landed; stage(it+1) may be in flight
        __syncthreads();

        if (it < 6) {                             // issue stage(it+2)
            int k0n = (it + 2) * KC;
            int nbuf = buf + 2; if (nbuf >= NSTAGE) nbuf -= NSTAGE;
            uint32_t* An  = smem + nbuf * STAGE_WORDS;
            uint32_t* BHn = An + OFF_BH;
            cp16(&An[ar * 20 + akq],     &a_gp[k0n]);
            cp16(&An[ar * 20 + akq + 4], &a_gp[k0n + 4]);
            const uint32_t* sH = WHbase + (k0n + bk) * 256 + bc;
            cp16(&BHn[bk * 136 + bc],     &sH[0]);
            cp16(&BHn[bk * 136 + bc + 4], &sH[4]);
            asm volatile("cp.async.commit_group;");
        } else {
            asm volatile("cp.async.commit_group;");   // keep group count consistent for wait_group 1
        }

        #pragma unroll
        for (int ks = 0; ks < KC; ks += 8) {
            uint32_t a[2][4];
            #pragma unroll
            for (int mi = 0; mi < 2; mi++) {
                int r = m_base + mi * 16 + g;
                a[mi][0] = As[r * 20 + ks + tig];
                a[mi][1] = As[(r + 8) * 20 + ks + tig];
                a[mi][2] = As[r * 20 + ks + tig + 4];
                a[mi][3] = As[(r + 8) * 20 + ks + tig + 4];
            }
            #pragma unroll
            for (int ni = 0; ni < 8; ni++) {
                int cc = n_base + ni * 8 + g;
                uint32_t b0 = BsH[(ks + tig) * 136 + cc];
                uint32_t b1 = BsH[(ks + tig + 4) * 136 + cc];
                #pragma unroll
                for (int mi = 0; mi < 2; mi++)
                    mma_tf32(c[mi][ni], a[mi], b0, b1);
            }
        }
        buf++; if (buf == NSTAGE) buf = 0;
    }

    // --- epilogue ---
    const float* bias = yhalf ? br_ : bl_;
    float* dst = yhalf ? g_xr : g_xl;
    #pragma unroll
    for (int ni = 0; ni < 8; ni++) {
        int cn = n_base + ni * 8 + tig * 2;
        float b0 = bias[cn], b1 = bias[cn + 1];
        #pragma unroll
        for (int mi = 0; mi < 2; mi++) {
            int ra = row0 + m_base + mi * 16 + g;
            int rb = ra + 8;
            if (ra < NN)
                *(float2*)&dst[(size_t)ra * DD + cn] = make_float2(c[mi][ni][0] + b0, c[mi][ni][1] + b1);
            if (rb < NN)
                *(float2*)&dst[(size_t)rb * DD + cn] = make_float2(c[mi][ni][2] + b0, c[mi][ni][3] + b1);
        }
    }
}

// ---------------- attention: warp per node, no-max softmax, ILP-4 + prefetch ----------------
__device__ __forceinline__ float dleaky(float4 c, float4 xr, float4 a, float d) {
    float v;
    v = c.x + xr.x; v = (v > 0.f) ? v : 0.2f * v; d = fmaf(v, a.x, d);
    v = c.y + xr.y; v = (v > 0.f) ? v : 0.2f * v; d = fmaf(v, a.y, d);
    v = c.z + xr.z; v = (v > 0.f) ? v : 0.2f * v; d = fmaf(v, a.z, d);
    v = c.w + xr.w; v = (v > 0.f) ? v : 0.2f * v; d = fmaf(v, a.w, d);
    return d;
}

__global__ void attn(const float* __restrict__ avec, const float* __restrict__ bvec,
                     float* __restrict__ outp) {
    const unsigned FULL = 0xffffffffu;
    int w = (blockIdx.x * blockDim.x + threadIdx.x) >> 5;
    if (w >= NN) return;
    int lane = threadIdx.x & 31;

    float4 xr4 = *(float4*)&g_xr[(size_t)w * DD + lane * 4];
    float4 a4  = *(const float4*)&avec[lane * 4];

    int p   = (w > 0) ? g_offs[w - 1] : 0;   // post-fill: g_offs[d] = end of segment d
    int end = g_offs[w];
    float s = 0.f;
    float ax = 0.f, ay = 0.f, az = 0.f, aw = 0.f;

    int p4end = p + ((end - p) & ~3);

    float4 c0, c1, c2, c3;
    if (p < p4end) {
        int s0 = g_srcs[p], s1 = g_srcs[p + 1], s2 = g_srcs[p + 2], s3 = g_srcs[p + 3];
        c0 = *(const float4*)&g_xl[(size_t)s0 * DD + lane * 4];
        c1 = *(const float4*)&g_xl[(size_t)s1 * DD + lane * 4];
        c2 = *(const float4*)&g_xl[(size_t)s2 * DD + lane * 4];
        c3 = *(const float4*)&g_xl[(size_t)s3 * DD + lane * 4];
    }

    while (p < p4end) {
        float4 u0 = c0, u1 = c1, u2 = c2, u3 = c3;
        int pn = p + 4;
        if (pn < p4end) {
            int s0 = g_srcs[pn], s1 = g_srcs[pn + 1], s2 = g_srcs[pn + 2], s3 = g_srcs[pn + 3];
            c0 = *(const float4*)&g_xl[(size_t)s0 * DD + lane * 4];
            c1 = *(const float4*)&g_xl[(size_t)s1 * DD + lane * 4];
            c2 = *(const float4*)&g_xl[(size_t)s2 * DD + lane * 4];
            c3 = *(const float4*)&g_xl[(size_t)s3 * DD + lane * 4];
        }

        float d0 = dleaky(u0, xr4, a4, 0.f);
        float d1 = dleaky(u1, xr4, a4, 0.f);
        float d2 = dleaky(u2, xr4, a4, 0.f);
        float d3 = dleaky(u3, xr4, a4, 0.f);

        #pragma unroll
        for (int off = 16; off >= 1; off >>= 1) {
            d0 += __shfl_xor_sync(FULL, d0, off);
            d1 += __shfl_xor_sync(FULL, d1, off);
            d2 += __shfl_xor_sync(FULL, d2, off);
            d3 += __shfl_xor_sync(FULL, d3, off);
        }

        float w0 = __expf(d0), w1 = __expf(d1), w2 = __expf(d2), w3 = __expf(d3);
        s += (w0 + w1) + (w2 + w3);
        ax += w0 * u0.x + w1 * u1.x + w2 * u2.x + w3 * u3.x;
        ay += w0 * u0.y + w1 * u1.y + w2 * u2.y + w3 * u3.y;
        az += w0 * u0.z + w1 * u1.z + w2 * u2.z + w3 * u3.z;
        aw += w0 * u0.w + w1 * u1.w + w2 * u2.w + w3 * u3.w;
        p = pn;
    }

    while (p < end) {
        int s0 = g_srcs[p];
        float4 u0 = *(const float4*)&g_xl[(size_t)s0 * DD + lane * 4];
        float d0 = dleaky(u0, xr4, a4, 0.f);
        #pragma unroll
        for (int off = 16; off >= 1; off >>= 1)
            d0 += __shfl_xor_sync(FULL, d0, off);
        float w0 = __expf(d0);
        s += w0;
        ax += w0 * u0.x;
        ay += w0 * u0.y;
        az += w0 * u0.z;
        aw += w0 * u0.w;
        p++;
    }

    float inv = 1.f / s;
    float4 b4 = *(const float4*)&bvec[lane * 4];
    float4 r = make_float4(ax * inv + b4.x, ay * inv + b4.y,
                           az * inv + b4.z, aw * inv + b4.w);
    if (outp) {
        *(float4*)&outp[(size_t)w * DD + lane * 4] = r;
    } else {
        uint4 t;
        t.x = f2tf32(fmaxf(r.x, 0.f));
        t.y = f2tf32(fmaxf(r.y, 0.f));
        t.z = f2tf32(fmaxf(r.z, 0.f));
        t.w = f2tf32(fmaxf(r.w, 0.f));
        *(uint4*)&g_htf[(size_t)w * DD + lane * 4] = t;
    }
}

// ---------------- launch ----------------
extern "C" void kernel_launch(void* const* d_in, const int* in_sizes, int n_in,
                              void* d_out, int out_size) {
    const float* x    = (const float*)d_in[0];
    const int*   ei   = (const int*)d_in[1];
    const float* Wl0  = (const float*)d_in[2];
    const float* Wr0  = (const float*)d_in[3];
    const float* bl0  = (const float*)d_in[4];
    const float* br0  = (const float*)d_in[5];
    const float* Wl   = (const float*)d_in[6];
    const float* Wr   = (const float*)d_in[7];
    const float* bl   = (const float*)d_in[8];
    const float* br   = (const float*)d_in[9];
    const float* att  = (const float*)d_in[10];
    const float* bias = (const float*)d_in[11];
    float* out = (float*)d_out;

    cudaFuncSetAttribute(gemm_tc, cudaFuncAttributeMaxDynamicSharedMemorySize, GEMM_SMEM_BYTES);

    zero_counts<<<(NN + 255) / 256, 256>>>();
    count_edges<<<(ETOT + 255) / 256, 256>>>(ei);
    scan_block<<<NBSCAN, 256>>>();
    scan_spine<<<1, 64>>>();
    scan_fix<<<(NN + 255) / 256, 256>>>();
    fill_edges<<<(ETOT + 255) / 256, 256>>>(ei);
    split_w<<<(4 * 128 * 256 + 255) / 256, 256>>>(Wl, Wr);

    const int attn_blocks = (NN * 32 + 255) / 256;
    dim3 tc_grid((NN + 127) / 128, 2);

    gemm0<<<NN, 256>>>(x, Wl0, Wr0, bl0, br0);
    attn<<<attn_blocks, 256>>>(att, bias, nullptr);

    for (int t = 1; t < 5; t++) {
        gemm_tc<<<tc_grid, 256, GEMM_SMEM_BYTES>>>(t - 1, bl + (size_t)(t - 1) * 128,
                                                   br + (size_t)(t - 1) * 128);
        attn<<<attn_blocks, 256>>>(att + (size_t)t * 128, bias + (size_t)t * 128,
                                   (t == 4) ? out : nullptr);
    }
}

// round 15
// speedup vs baseline: 1.1482x; 1.0532x over previous
#include <cuda_runtime.h>
#include <cuda_fp16.h>
#include <cstdint>

#define NN 50000
#define EE 800000
#define ETOT (EE + NN)
#define DD 128
#define NROWS_PAD 50048
#define NBSCAN ((NN + 1023) / 1024)

// ---------------- static device scratch ----------------
__device__ uint32_t g_htf[NROWS_PAD * DD];   // tf32(relu(h)) — produced by attn, consumed by gemm A
__device__ __half g_xlh[NN * DD];            // xl in fp16 (attn gather operand)
__device__ float g_xr[NN * DD];
__device__ int   g_deg[NN];
__device__ int   g_offs[NN + 1];
__device__ int   g_srcs[ETOT];
__device__ int   g_bsums[NBSCAN];
// pre-converted tf32 weights: [layer][k][col 0..255 = Wl|Wr]
__device__ uint32_t g_WH[4 * 128 * 256];

__device__ __forceinline__ uint32_t f2tf32(float x) {
    uint32_t r;
    asm volatile("cvt.rna.tf32.f32 %0, %1;" : "=r"(r) : "f"(x));
    return r;
}

// ---------------- CSR build ----------------
__global__ void zero_counts() {
    int i = blockIdx.x * blockDim.x + threadIdx.x;
    if (i < NN) g_deg[i] = 0;
}

__global__ void count_edges(const int* __restrict__ ei) {
    int t = blockIdx.x * blockDim.x + threadIdx.x;
    if (t < ETOT) {
        int dst = (t < EE) ? ei[EE + t] : (t - EE);
        atomicAdd(&g_deg[dst], 1);
    }
}

__global__ void scan_block() {
    __shared__ int sm[256];
    int t = threadIdx.x;
    int base = blockIdx.x * 1024 + t * 4;
    int v0 = (base + 0 < NN) ? g_deg[base + 0] : 0;
    int v1 = (base + 1 < NN) ? g_deg[base + 1] : 0;
    int v2 = (base + 2 < NN) ? g_deg[base + 2] : 0;
    int v3 = (base + 3 < NN) ? g_deg[base + 3] : 0;
    v1 += v0; v2 += v1; v3 += v2;
    sm[t] = v3;
    __syncthreads();
    #pragma unroll
    for (int off = 1; off < 256; off <<= 1) {
        int add = (t >= off) ? sm[t - off] : 0;
        __syncthreads();
        sm[t] += add;
        __syncthreads();
    }
    int prev = (t > 0) ? sm[t - 1] : 0;
    if (base + 0 < NN) g_offs[base + 0] = prev + v0;
    if (base + 1 < NN) g_offs[base + 1] = prev + v1;
    if (base + 2 < NN) g_offs[base + 2] = prev + v2;
    if (base + 3 < NN) g_offs[base + 3] = prev + v3;
    if (t == 255) g_bsums[blockIdx.x] = sm[255];
}

__global__ void scan_spine() {
    __shared__ int sm[64];
    int t = threadIdx.x;
    sm[t] = (t < NBSCAN) ? g_bsums[t] : 0;
    __syncthreads();
    #pragma unroll
    for (int off = 1; off < 64; off <<= 1) {
        int add = (t >= off) ? sm[t - off] : 0;
        __syncthreads();
        sm[t] += add;
        __syncthreads();
    }
    if (t < NBSCAN) g_bsums[t] = (t > 0) ? sm[t - 1] : 0;
}

__global__ void scan_fix() {
    int i = blockIdx.x * blockDim.x + threadIdx.x;
    if (i < NN) g_offs[i] = g_offs[i] - g_deg[i] + g_bsums[i >> 10];
}

__global__ void fill_edges(const int* __restrict__ ei) {
    int t = blockIdx.x * blockDim.x + threadIdx.x;
    if (t < ETOT) {
        int src, dst;
        if (t < EE) { src = ei[t]; dst = ei[EE + t]; }
        else        { src = t - EE; dst = src; }
        int pos = atomicAdd(&g_offs[dst], 1);
        g_srcs[pos] = src;
    }
}

// ---------------- weight pre-convert (tf32) ----------------
__global__ void split_w(const float* __restrict__ Wl, const float* __restrict__ Wr) {
    int i = blockIdx.x * blockDim.x + threadIdx.x;
    if (i >= 4 * 128 * 256) return;
    int layer = i >> 15;
    int rem = i & 32767;
    int k = rem >> 8;
    int c = rem & 255;
    float v = (c < 128) ? Wl[layer * 16384 + k * 128 + c]
                        : Wr[layer * 16384 + k * 128 + (c - 128)];
    g_WH[i] = f2tf32(v);
}

// ---------------- layer 0 GEMM (K=7) ----------------
__global__ void gemm0(const float* __restrict__ x,
                      const float* __restrict__ Wl0, const float* __restrict__ Wr0,
                      const float* __restrict__ bl0, const float* __restrict__ br0) {
    int node = blockIdx.x;
    int j = threadIdx.x;
    __shared__ float xs[7];
    if (j < 7) xs[j] = x[node * 7 + j];
    __syncthreads();
    const float* W = (j < 128) ? Wl0 : Wr0;
    int c = j & 127;
    float acc = (j < 128) ? bl0[c] : br0[c];
    #pragma unroll
    for (int k = 0; k < 7; k++) acc += xs[k] * W[k * 128 + c];
    if (j < 128) g_xlh[node * DD + c] = __float2half_rn(acc);
    else         g_xr[node * DD + c] = acc;
}

// ---------------- TC GEMM (r13: 128x128 per yhalf, occ 2, 3-stage cp.async) ----------------
#define KC 16
#define STAGE_WORDS 4736
#define OFF_BH 2560
#define NSTAGE 3
#define GEMM_SMEM_BYTES (NSTAGE * STAGE_WORDS * 4)

__device__ __forceinline__ void mma_tf32(float c[4], const uint32_t a[4], uint32_t b0, uint32_t b1) {
    asm volatile(
        "mma.sync.aligned.m16n8k8.row.col.f32.tf32.tf32.f32 "
        "{%0,%1,%2,%3}, {%4,%5,%6,%7}, {%8,%9}, {%0,%1,%2,%3};"
        : "+f"(c[0]), "+f"(c[1]), "+f"(c[2]), "+f"(c[3])
        : "r"(a[0]), "r"(a[1]), "r"(a[2]), "r"(a[3]), "r"(b0), "r"(b1));
}

__device__ __forceinline__ void cp16(uint32_t* dst_smem, const uint32_t* src_gmem) {
    uint32_t saddr = (uint32_t)__cvta_generic_to_shared(dst_smem);
    asm volatile("cp.async.cg.shared.global [%0], [%1], 16;" :: "r"(saddr), "l"(src_gmem));
}

__global__ __launch_bounds__(256, 2) void gemm_tc(int layer,
                                                  const float* __restrict__ bl_,
                                                  const float* __restrict__ br_) {
    extern __shared__ uint32_t smem[];

    int tid  = threadIdx.x;
    int lane = tid & 31;
    int wid  = tid >> 5;
    int g    = lane >> 2;
    int tig  = lane & 3;
    int wm   = wid >> 1;
    int wn   = wid & 1;
    int m_base = wm * 32;
    int n_base = wn * 64;
    int row0 = blockIdx.x * 128;
    int yhalf = blockIdx.y;

    const uint32_t* WHbase = g_WH + layer * 32768 + yhalf * 128;

    float c[2][8][4];
    #pragma unroll
    for (int mi = 0; mi < 2; mi++)
        #pragma unroll
        for (int ni = 0; ni < 8; ni++)
            #pragma unroll
            for (int q = 0; q < 4; q++) c[mi][ni][q] = 0.f;

    int ar  = tid >> 1;
    int akq = (tid & 1) * 8;
    int bk  = tid >> 4;
    int bc  = (tid & 15) * 8;
    const uint32_t* a_gp = &g_htf[(size_t)(row0 + ar) * DD + akq];

    #pragma unroll
    for (int st = 0; st < 2; st++) {
        uint32_t* As = smem + st * STAGE_WORDS;
        uint32_t* BH = As + OFF_BH;
        int k0 = st * KC;
        cp16(&As[ar * 20 + akq],     &a_gp[k0]);
        cp16(&As[ar * 20 + akq + 4], &a_gp[k0 + 4]);
        const uint32_t* sH = WHbase + (k0 + bk) * 256 + bc;
        cp16(&BH[bk * 136 + bc],     &sH[0]);
        cp16(&BH[bk * 136 + bc + 4], &sH[4]);
        asm volatile("cp.async.commit_group;");
    }

    int buf = 0;
    for (int it = 0; it < 8; it++) {
        uint32_t* As  = smem + buf * STAGE_WORDS;
        uint32_t* BsH = As + OFF_BH;

        asm volatile("cp.async.wait_group 1;");
        __syncthreads();

        if (it < 6) {
            int k0n = (it + 2) * KC;
            int nbuf = buf + 2; if (nbuf >= NSTAGE) nbuf -= NSTAGE;
            uint32_t* An  = smem + nbuf * STAGE_WORDS;
            uint32_t* BHn = An + OFF_BH;
            cp16(&An[ar * 20 + akq],     &a_gp[k0n]);
            cp16(&An[ar * 20 + akq + 4], &a_gp[k0n + 4]);
            const uint32_t* sH = WHbase + (k0n + bk) * 256 + bc;
            cp16(&BHn[bk * 136 + bc],     &sH[0]);
            cp16(&BHn[bk * 136 + bc + 4], &sH[4]);
            asm volatile("cp.async.commit_group;");
        } else {
            asm volatile("cp.async.commit_group;");
        }

        #pragma unroll
        for (int ks = 0; ks < KC; ks += 8) {
            uint32_t a[2][4];
            #pragma unroll
            for (int mi = 0; mi < 2; mi++) {
                int r = m_base + mi * 16 + g;
                a[mi][0] = As[r * 20 + ks + tig];
                a[mi][1] = As[(r + 8) * 20 + ks + tig];
                a[mi][2] = As[r * 20 + ks + tig + 4];
                a[mi][3] = As[(r + 8) * 20 + ks + tig + 4];
            }
            #pragma unroll
            for (int ni = 0; ni < 8; ni++) {
                int cc = n_base + ni * 8 + g;
                uint32_t b0 = BsH[(ks + tig) * 136 + cc];
                uint32_t b1 = BsH[(ks + tig + 4) * 136 + cc];
                #pragma unroll
                for (int mi = 0; mi < 2; mi++)
                    mma_tf32(c[mi][ni], a[mi], b0, b1);
            }
        }
        buf++; if (buf == NSTAGE) buf = 0;
    }

    // --- epilogue: yhalf=0 -> fp16 xl, yhalf=1 -> fp32 xr ---
    if (yhalf == 0) {
        #pragma unroll
        for (int ni = 0; ni < 8; ni++) {
            int cn = n_base + ni * 8 + tig * 2;
            float b0 = bl_[cn], b1 = bl_[cn + 1];
            #pragma unroll
            for (int mi = 0; mi < 2; mi++) {
                int ra = row0 + m_base + mi * 16 + g;
                int rb = ra + 8;
                if (ra < NN)
                    *(__half2*)&g_xlh[(size_t)ra * DD + cn] =
                        __floats2half2_rn(c[mi][ni][0] + b0, c[mi][ni][1] + b1);
                if (rb < NN)
                    *(__half2*)&g_xlh[(size_t)rb * DD + cn] =
                        __floats2half2_rn(c[mi][ni][2] + b0, c[mi][ni][3] + b1);
            }
        }
    } else {
        #pragma unroll
        for (int ni = 0; ni < 8; ni++) {
            int cn = n_base + ni * 8 + tig * 2;
            float b0 = br_[cn], b1 = br_[cn + 1];
            #pragma unroll
            for (int mi = 0; mi < 2; mi++) {
                int ra = row0 + m_base + mi * 16 + g;
                int rb = ra + 8;
                if (ra < NN)
                    *(float2*)&g_xr[(size_t)ra * DD + cn] =
                        make_float2(c[mi][ni][0] + b0, c[mi][ni][1] + b1);
                if (rb < NN)
                    *(float2*)&g_xr[(size_t)rb * DD + cn] =
                        make_float2(c[mi][ni][2] + b0, c[mi][ni][3] + b1);
            }
        }
    }
}

// ---------------- attention: warp per node, no-max softmax, ILP-4 + prefetch, fp16 gather ----------------
__device__ __forceinline__ float4 h4_to_f4(uint2 r) {
    float2 f0 = __half22float2(*reinterpret_cast<const __half2*>(&r.x));
    float2 f1 = __half22float2(*reinterpret_cast<const __half2*>(&r.y));
    return make_float4(f0.x, f0.y, f1.x, f1.y);
}

__device__ __forceinline__ float dleaky(float4 c, float4 xr, float4 a, float d) {
    float v;
    v = c.x + xr.x; v = (v > 0.f) ? v : 0.2f * v; d = fmaf(v, a.x, d);
    v = c.y + xr.y; v = (v > 0.f) ? v : 0.2f * v; d = fmaf(v, a.y, d);
    v = c.z + xr.z; v = (v > 0.f) ? v : 0.2f * v; d = fmaf(v, a.z, d);
    v = c.w + xr.w; v = (v > 0.f) ? v : 0.2f * v; d = fmaf(v, a.w, d);
    return d;
}

__global__ void attn(const float* __restrict__ avec, const float* __restrict__ bvec,
                     float* __restrict__ outp) {
    const unsigned FULL = 0xffffffffu;
    int w = (blockIdx.x * blockDim.x + threadIdx.x) >> 5;
    if (w >= NN) return;
    int lane = threadIdx.x & 31;

    float4 xr4 = *(float4*)&g_xr[(size_t)w * DD + lane * 4];
    float4 a4  = *(const float4*)&avec[lane * 4];

    int p   = (w > 0) ? g_offs[w - 1] : 0;
    int end = g_offs[w];
    float s = 0.f;
    float ax = 0.f, ay = 0.f, az = 0.f, aw = 0.f;

    int p4end = p + ((end - p) & ~3);

    uint2 r0, r1, r2, r3;
    if (p < p4end) {
        int s0 = g_srcs[p], s1 = g_srcs[p + 1], s2 = g_srcs[p + 2], s3 = g_srcs[p + 3];
        r0 = *(const uint2*)&g_xlh[(size_t)s0 * DD + lane * 4];
        r1 = *(const uint2*)&g_xlh[(size_t)s1 * DD + lane * 4];
        r2 = *(const uint2*)&g_xlh[(size_t)s2 * DD + lane * 4];
        r3 = *(const uint2*)&g_xlh[(size_t)s3 * DD + lane * 4];
    }

    while (p < p4end) {
        float4 u0 = h4_to_f4(r0), u1 = h4_to_f4(r1), u2 = h4_to_f4(r2), u3 = h4_to_f4(r3);
        int pn = p + 4;
        if (pn < p4end) {
            int s0 = g_srcs[pn], s1 = g_srcs[pn + 1], s2 = g_srcs[pn + 2], s3 = g_srcs[pn + 3];
            r0 = *(const uint2*)&g_xlh[(size_t)s0 * DD + lane * 4];
            r1 = *(const uint2*)&g_xlh[(size_t)s1 * DD + lane * 4];
            r2 = *(const uint2*)&g_xlh[(size_t)s2 * DD + lane * 4];
            r3 = *(const uint2*)&g_xlh[(size_t)s3 * DD + lane * 4];
        }

        float d0 = dleaky(u0, xr4, a4, 0.f);
        float d1 = dleaky(u1, xr4, a4, 0.f);
        float d2 = dleaky(u2, xr4, a4, 0.f);
        float d3 = dleaky(u3, xr4, a4, 0.f);

        #pragma unroll
        for (int off = 16; off >= 1; off >>= 1) {
            d0 += __shfl_xor_sync(FULL, d0, off);
            d1 += __shfl_xor_sync(FULL, d1, off);
            d2 += __shfl_xor_sync(FULL, d2, off);
            d3 += __shfl_xor_sync(FULL, d3, off);
        }

        float w0 = __expf(d0), w1 = __expf(d1), w2 = __expf(d2), w3 = __expf(d3);
        s += (w0 + w1) + (w2 + w3);
        ax += w0 * u0.x + w1 * u1.x + w2 * u2.x + w3 * u3.x;
        ay += w0 * u0.y + w1 * u1.y + w2 * u2.y + w3 * u3.y;
        az += w0 * u0.z + w1 * u1.z + w2 * u2.z + w3 * u3.z;
        aw += w0 * u0.w + w1 * u1.w + w2 * u2.w + w3 * u3.w;
        p = pn;
    }

    while (p < end) {
        int s0 = g_srcs[p];
        float4 u0 = h4_to_f4(*(const uint2*)&g_xlh[(size_t)s0 * DD + lane * 4]);
        float d0 = dleaky(u0, xr4, a4, 0.f);
        #pragma unroll
        for (int off = 16; off >= 1; off >>= 1)
            d0 += __shfl_xor_sync(FULL, d0, off);
        float w0 = __expf(d0);
        s += w0;
        ax += w0 * u0.x;
        ay += w0 * u0.y;
        az += w0 * u0.z;
        aw += w0 * u0.w;
        p++;
    }

    float inv = 1.f / s;
    float4 b4 = *(const float4*)&bvec[lane * 4];
    float4 r = make_float4(ax * inv + b4.x, ay * inv + b4.y,
                           az * inv + b4.z, aw * inv + b4.w);
    if (outp) {
        *(float4*)&outp[(size_t)w * DD + lane * 4] = r;
    } else {
        uint4 t;
        t.x = f2tf32(fmaxf(r.x, 0.f));
        t.y = f2tf32(fmaxf(r.y, 0.f));
        t.z = f2tf32(fmaxf(r.z, 0.f));
        t.w = f2tf32(fmaxf(r.w, 0.f));
        *(uint4*)&g_htf[(size_t)w * DD + lane * 4] = t;
    }
}

// ---------------- launch ----------------
extern "C" void kernel_launch(void* const* d_in, const int* in_sizes, int n_in,
                              void* d_out, int out_size) {
    const float* x    = (const float*)d_in[0];
    const int*   ei   = (const int*)d_in[1];
    const float* Wl0  = (const float*)d_in[2];
    const float* Wr0  = (const float*)d_in[3];
    const float* bl0  = (const float*)d_in[4];
    const float* br0  = (const float*)d_in[5];
    const float* Wl   = (const float*)d_in[6];
    const float* Wr   = (const float*)d_in[7];
    const float* bl   = (const float*)d_in[8];
    const float* br   = (const float*)d_in[9];
    const float* att  = (const float*)d_in[10];
    const float* bias = (const float*)d_in[11];
    float* out = (float*)d_out;

    cudaFuncSetAttribute(gemm_tc, cudaFuncAttributeMaxDynamicSharedMemorySize, GEMM_SMEM_BYTES);

    zero_counts<<<(NN + 255) / 256, 256>>>();
    count_edges<<<(ETOT + 255) / 256, 256>>>(ei);
    scan_block<<<NBSCAN, 256>>>();
    scan_spine<<<1, 64>>>();
    scan_fix<<<(NN + 255) / 256, 256>>>();
    fill_edges<<<(ETOT + 255) / 256, 256>>>(ei);
    split_w<<<(4 * 128 * 256 + 255) / 256, 256>>>(Wl, Wr);

    const int attn_blocks = (NN * 32 + 255) / 256;
    dim3 tc_grid((NN + 127) / 128, 2);

    gemm0<<<NN, 256>>>(x, Wl0, Wr0, bl0, br0);
    attn<<<attn_blocks, 256>>>(att, bias, nullptr);

    for (int t = 1; t < 5; t++) {
        gemm_tc<<<tc_grid, 256, GEMM_SMEM_BYTES>>>(t - 1, bl + (size_t)(t - 1) * 128,
                                                   br + (size_t)(t - 1) * 128);
        attn<<<attn_blocks, 256>>>(att + (size_t)t * 128, bias + (size_t)t * 128,
                                   (t == 4) ? out : nullptr);
    }
}